// round 2
// baseline (speedup 1.0000x reference)
#include <cuda_runtime.h>

#define PSSM_BATCH  2
#define PSSM_SEQ    2048
#define PSSM_DIN    128
#define PSSM_NST    64
#define PSSM_LOG2E  1.4426950408889634f

// ---- scratch (static device arrays; no allocation) ----
__device__ float g_xc   [PSSM_BATCH*PSSM_DIN*PSSM_SEQ];   // (b,d,l)
__device__ float g_delta[PSSM_BATCH*PSSM_DIN*PSSM_SEQ];   // (b,d,l)  sigmoid applied
__device__ float g_u    [PSSM_BATCH*PSSM_DIN*PSSM_SEQ];   // (b,d,l)  delta*x_conv
__device__ float g_B    [PSSM_BATCH*PSSM_SEQ*PSSM_NST];   // (b,l,n)
__device__ float g_C    [PSSM_BATCH*PSSM_SEQ*PSSM_NST];   // (b,l,n)
__device__ float g_a2   [PSSM_NST];                       // rowsum(A)*log2(e)

// ============================================================
// Stage 1: projection xp = x @ W^T, split + sigmoid + layouts
// grid (32, 6), block 128.  token = bx*128+tx, og = by (64 outs each)
// ============================================================
__global__ void pssm_proj_kernel(const float* __restrict__ x,
                                 const float* __restrict__ W,
                                 const float* __restrict__ A)
{
    if (blockIdx.x == 0 && blockIdx.y == 0 && threadIdx.x < PSSM_NST) {
        float s = 0.f;
        const float* ar = A + threadIdx.x * PSSM_NST;
        #pragma unroll 8
        for (int j = 0; j < PSSM_NST; j++) s += ar[j];
        g_a2[threadIdx.x] = s * PSSM_LOG2E;
    }

    const int token = blockIdx.x * blockDim.x + threadIdx.x;   // 0..4095
    const int og    = blockIdx.y;                              // 0..5
    const int b = token >> 11;
    const int l = token & 2047;

    float4 xv[16];
    const float4* xr = (const float4*)(x + token * 64);
    #pragma unroll
    for (int i = 0; i < 16; i++) xv[i] = __ldg(&xr[i]);

    for (int i = 0; i < 64; i++) {
        const int o = og * 64 + i;
        const float4* wr = (const float4*)(W + o * 64);
        float a0 = 0.f, a1 = 0.f, a2 = 0.f, a3 = 0.f;
        #pragma unroll
        for (int k = 0; k < 16; k++) {
            float4 w4 = __ldg(&wr[k]);
            a0 = fmaf(w4.x, xv[k].x, a0);
            a1 = fmaf(w4.y, xv[k].y, a1);
            a2 = fmaf(w4.z, xv[k].z, a2);
            a3 = fmaf(w4.w, xv[k].w, a3);
        }
        const float acc = (a0 + a1) + (a2 + a3);

        if (og < 2) {                         // x_c_in channels 0..127
            g_xc[(b * PSSM_DIN + o) * PSSM_SEQ + l] = acc;
        } else if (og < 4) {                  // delta_raw channels 0..127
            const int d = o - 128;
            g_delta[(b * PSSM_DIN + d) * PSSM_SEQ + l] =
                __fdividef(1.f, 1.f + __expf(-acc));
        } else if (og == 4) {                 // B
            g_B[(b * PSSM_SEQ + l) * PSSM_NST + (o - 256)] = acc;
        } else {                              // C
            g_C[(b * PSSM_SEQ + l) * PSSM_NST + (o - 320)] = acc;
        }
    }
}

// ============================================================
// Stage 2: depthwise causal conv (k=4) + bias, u = delta*x_conv,
//          y base = D * x_conv
// ============================================================
__global__ void pssm_conv_kernel(const float* __restrict__ cw,
                                 const float* __restrict__ cb,
                                 const float* __restrict__ Dp,
                                 float* __restrict__ y)
{
    const int idx = blockIdx.x * blockDim.x + threadIdx.x;   // (b,d,l) flat
    const int l  = idx & 2047;
    const int bd = idx >> 11;
    const int d  = bd & 127;
    const int b  = bd >> 7;

    const float* xc = g_xc + bd * PSSM_SEQ;
    const float w0 = __ldg(&cw[d * 4 + 0]);
    const float w1 = __ldg(&cw[d * 4 + 1]);
    const float w2 = __ldg(&cw[d * 4 + 2]);
    const float w3 = __ldg(&cw[d * 4 + 3]);

    float v = __ldg(&cb[d]);
    v = fmaf(w3, xc[l], v);
    if (l >= 1) v = fmaf(w2, xc[l - 1], v);
    if (l >= 2) v = fmaf(w1, xc[l - 2], v);
    if (l >= 3) v = fmaf(w0, xc[l - 3], v);

    g_u[idx] = g_delta[idx] * v;
    y[(b * PSSM_SEQ + l) * PSSM_DIN + d] = __ldg(&Dp[d]) * v;
}

// ============================================================
// Stage 3: bidirectional scan.
// 128 blocks: blk = dir*64 + b*32 + dgroup; 8 warps/block:
//   warp = (d_in_group 0..3, n_half 0..1), one state per lane.
// B/C chunk (64 timesteps) staged in shared, shared by 4 d.
// y += sum_n C*h via butterfly + lane0 atomicAdd.
// ============================================================
template<bool REV>
__device__ __forceinline__ void pssm_scan_chunk(
    const float* __restrict__ dl, const float* __restrict__ ul, int l0,
    const float* __restrict__ Bs, const float* __restrict__ Cs,
    float a2n, float& h, float* __restrict__ ybase, int n, int lane)
{
    #pragma unroll 4
    for (int s = 0; s < 16; s++) {
        const int lb = REV ? (60 - 4 * s) : 4 * s;
        const float4 d4 = __ldg((const float4*)(dl + l0 + lb));
        const float4 u4 = __ldg((const float4*)(ul + l0 + lb));
        const float da[4] = {d4.x, d4.y, d4.z, d4.w};
        const float ua[4] = {u4.x, u4.y, u4.z, u4.w};
        #pragma unroll
        for (int k = 0; k < 4; k++) {
            const int j = REV ? (3 - k) : k;      // compile-time
            const int l = lb + j;
            const float e  = exp2f(da[j] * a2n);
            const float Bv = Bs[l * PSSM_NST + n];
            const float Cv = Cs[l * PSSM_NST + n];
            h = fmaf(e, h, ua[j] * Bv);
            float p = Cv * h;
            p += __shfl_xor_sync(0xffffffffu, p, 16);
            p += __shfl_xor_sync(0xffffffffu, p, 8);
            p += __shfl_xor_sync(0xffffffffu, p, 4);
            p += __shfl_xor_sync(0xffffffffu, p, 2);
            p += __shfl_xor_sync(0xffffffffu, p, 1);
            if (lane == 0) atomicAdd(&ybase[l * PSSM_DIN], p);
        }
    }
}

__global__ void __launch_bounds__(256) pssm_scan_kernel(float* __restrict__ y)
{
    __shared__ float Bs[64 * PSSM_NST];
    __shared__ float Cs[64 * PSSM_NST];

    const int blk  = blockIdx.x;          // 0..127
    const bool rev = blk >= 64;
    const int t    = blk & 63;
    const int b    = t >> 5;
    const int dg   = t & 31;

    const int warp = threadIdx.x >> 5;
    const int lane = threadIdx.x & 31;
    const int d    = dg * 4 + (warp >> 1);
    const int half = warp & 1;
    const int n    = half * 32 + lane;

    const float* dl = g_delta + (b * PSSM_DIN + d) * PSSM_SEQ;
    const float* ul = g_u     + (b * PSSM_DIN + d) * PSSM_SEQ;
    const float a2n = g_a2[n];
    float h = 0.f;

    float* yb = y + (size_t)(b * PSSM_SEQ) * PSSM_DIN + d;

    for (int c = 0; c < 32; c++) {
        const int cc = rev ? (31 - c) : c;
        const int l0 = cc * 64;

        // stage B/C chunk (contiguous 16KB each) into shared
        const float4* gB = (const float4*)(g_B + (b * PSSM_SEQ + l0) * PSSM_NST);
        const float4* gC = (const float4*)(g_C + (b * PSSM_SEQ + l0) * PSSM_NST);
        float4* sB = (float4*)Bs;
        float4* sC = (float4*)Cs;
        #pragma unroll
        for (int i = 0; i < 4; i++) {
            sB[threadIdx.x + 256 * i] = __ldg(&gB[threadIdx.x + 256 * i]);
            sC[threadIdx.x + 256 * i] = __ldg(&gC[threadIdx.x + 256 * i]);
        }
        __syncthreads();

        if (!rev) pssm_scan_chunk<false>(dl, ul, l0, Bs, Cs, a2n, h,
                                         yb + (size_t)l0 * PSSM_DIN, n, lane);
        else      pssm_scan_chunk<true >(dl, ul, l0, Bs, Cs, a2n, h,
                                         yb + (size_t)l0 * PSSM_DIN, n, lane);
        __syncthreads();
    }
}

// ============================================================
extern "C" void kernel_launch(void* const* d_in, const int* in_sizes, int n_in,
                              void* d_out, int out_size)
{
    const float* x  = (const float*)d_in[0];
    const float* W  = (const float*)d_in[1];
    const float* cw = (const float*)d_in[2];
    const float* cb = (const float*)d_in[3];
    const float* A  = (const float*)d_in[4];
    const float* Dp = (const float*)d_in[5];
    float* y = (float*)d_out;

    dim3 pg(32, 6);
    pssm_proj_kernel<<<pg, 128>>>(x, W, A);
    pssm_conv_kernel<<<(PSSM_BATCH * PSSM_DIN * PSSM_SEQ) / 256, 256>>>(cw, cb, Dp, y);
    pssm_scan_kernel<<<128, 256>>>(y);
}

// round 5
// speedup vs baseline: 2.8407x; 2.8407x over previous
#include <cuda_runtime.h>

#define PSSM_BATCH  2
#define PSSM_SEQ    2048
#define PSSM_DIN    128
#define PSSM_NST    64
#define PSSM_NC     32      // chunks per sequence
#define PSSM_CL     64      // chunk length
#define PSSM_LOG2E  1.4426950408889634f

// ---- scratch (static device arrays; no allocation) ----
__device__ float g_xc   [PSSM_BATCH*PSSM_DIN*PSSM_SEQ];            // (b,d,l)
__device__ float g_delta[PSSM_BATCH*PSSM_DIN*PSSM_SEQ];            // (b,d,l) sigmoid applied
__device__ float g_u    [PSSM_BATCH*PSSM_DIN*PSSM_SEQ];            // (b,d,l) delta*x_conv
__device__ float g_B    [PSSM_BATCH*PSSM_SEQ*PSSM_NST];            // (b,l,n)
__device__ float g_C    [PSSM_BATCH*PSSM_SEQ*PSSM_NST];            // (b,l,n)
__device__ float g_a2   [PSSM_NST];                                // rowsum(A)*log2(e)
__device__ float g_hloc [PSSM_BATCH*2*PSSM_NC*PSSM_DIN*PSSM_NST];  // (b,dir,c,d,n)
__device__ float g_carry[PSSM_BATCH*2*PSSM_NC*PSSM_DIN*PSSM_NST];  // (b,dir,c,d,n)
__device__ float g_dS   [PSSM_BATCH*PSSM_NC*PSSM_DIN];             // (b,c,d)

// ============================================================
// Stage 1: projection xp = x @ W^T, split + sigmoid + layouts
// grid (32, 24), block 128. token = bx*128+tx; 16 outputs/thread.
// ============================================================
__global__ void pssm_proj_kernel(const float* __restrict__ x,
                                 const float* __restrict__ W,
                                 const float* __restrict__ A)
{
    if (blockIdx.x == 0 && blockIdx.y == 0 && threadIdx.x < PSSM_NST) {
        float s = 0.f;
        const float* ar = A + threadIdx.x * PSSM_NST;
        #pragma unroll 8
        for (int j = 0; j < PSSM_NST; j++) s += ar[j];
        g_a2[threadIdx.x] = s * PSSM_LOG2E;
    }

    const int token = blockIdx.x * blockDim.x + threadIdx.x;   // 0..4095
    const int og    = blockIdx.y;                              // 0..23
    const int b = token >> 11;
    const int l = token & 2047;

    float4 xv[16];
    const float4* xr = (const float4*)(x + token * 64);
    #pragma unroll
    for (int i = 0; i < 16; i++) xv[i] = __ldg(&xr[i]);

    #pragma unroll 2
    for (int i = 0; i < 16; i++) {
        const int o = og * 16 + i;
        const float4* wr = (const float4*)(W + o * 64);
        float a0 = 0.f, a1 = 0.f, a2 = 0.f, a3 = 0.f;
        #pragma unroll
        for (int k = 0; k < 16; k++) {
            float4 w4 = __ldg(&wr[k]);
            a0 = fmaf(w4.x, xv[k].x, a0);
            a1 = fmaf(w4.y, xv[k].y, a1);
            a2 = fmaf(w4.z, xv[k].z, a2);
            a3 = fmaf(w4.w, xv[k].w, a3);
        }
        const float acc = (a0 + a1) + (a2 + a3);

        if (o < 128) {
            g_xc[(b * PSSM_DIN + o) * PSSM_SEQ + l] = acc;
        } else if (o < 256) {
            g_delta[(b * PSSM_DIN + (o - 128)) * PSSM_SEQ + l] =
                __fdividef(1.f, 1.f + __expf(-acc));
        } else if (o < 320) {
            g_B[(b * PSSM_SEQ + l) * PSSM_NST + (o - 256)] = acc;
        } else {
            g_C[(b * PSSM_SEQ + l) * PSSM_NST + (o - 320)] = acc;
        }
    }
}

// ============================================================
// Stage 2: depthwise causal conv (k=4) + bias, u = delta*x_conv,
//          y base = D * x_conv
// ============================================================
__global__ void pssm_conv_kernel(const float* __restrict__ cw,
                                 const float* __restrict__ cb,
                                 const float* __restrict__ Dp,
                                 float* __restrict__ y)
{
    const int idx = blockIdx.x * blockDim.x + threadIdx.x;   // (b,d,l) flat
    const int l  = idx & 2047;
    const int bd = idx >> 11;
    const int d  = bd & 127;
    const int b  = bd >> 7;

    const float* xc = g_xc + bd * PSSM_SEQ;
    const float w0 = __ldg(&cw[d * 4 + 0]);
    const float w1 = __ldg(&cw[d * 4 + 1]);
    const float w2 = __ldg(&cw[d * 4 + 2]);
    const float w3 = __ldg(&cw[d * 4 + 3]);

    float v = __ldg(&cb[d]);
    v = fmaf(w3, xc[l], v);
    if (l >= 1) v = fmaf(w2, xc[l - 1], v);
    if (l >= 2) v = fmaf(w1, xc[l - 2], v);
    if (l >= 3) v = fmaf(w0, xc[l - 3], v);

    g_u[idx] = g_delta[idx] * v;
    y[(b * PSSM_SEQ + l) * PSSM_DIN + d] = __ldg(&Dp[d]) * v;
}

// ============================================================
// Phase A: per-chunk local scan -> end state hloc, chunk delta-sum dS.
// grid 1024: blk = (b<<9)|(dir<<8)|(c<<3)|dg.  block 512 = 16 warps.
// warp -> d = dg*16 + warp; lane holds states (lane, lane+32).
// ============================================================
template<bool REV>
__device__ __forceinline__ void pssm_local_scan(
    const float* __restrict__ dl, const float* __restrict__ ul,
    const float* __restrict__ Bs, float a21, float a22, int lane,
    float& h1, float& h2, float& ds)
{
    #pragma unroll 4
    for (int s = 0; s < 16; s++) {
        const int lb = REV ? (60 - 4 * s) : 4 * s;
        const float4 d4 = __ldg((const float4*)(dl + lb));
        const float4 u4 = __ldg((const float4*)(ul + lb));
        const float da[4] = {d4.x, d4.y, d4.z, d4.w};
        const float ua[4] = {u4.x, u4.y, u4.z, u4.w};
        #pragma unroll
        for (int k = 0; k < 4; k++) {
            const int j = REV ? (3 - k) : k;          // compile-time
            const int l = lb + j;
            const float e1 = exp2f(da[j] * a21);
            const float e2 = exp2f(da[j] * a22);
            const float B1 = Bs[l * PSSM_NST + lane];
            const float B2 = Bs[l * PSSM_NST + lane + 32];
            h1 = fmaf(e1, h1, ua[j] * B1);
            h2 = fmaf(e2, h2, ua[j] * B2);
            ds += da[j];
        }
    }
}

__global__ void __launch_bounds__(512) pssm_scanA_kernel()
{
    __shared__ float Bs[PSSM_CL * PSSM_NST];   // 16KB

    const int blk = blockIdx.x;
    const int dg  = blk & 7;
    const int c   = (blk >> 3) & 31;
    const int dir = (blk >> 8) & 1;
    const int b   = blk >> 9;

    const int warp = threadIdx.x >> 5;
    const int lane = threadIdx.x & 31;
    const int d    = dg * 16 + warp;

    // stage B chunk
    const float* gB = g_B + (b * PSSM_SEQ + c * PSSM_CL) * PSSM_NST;
    for (int f = threadIdx.x; f < PSSM_CL * PSSM_NST; f += 512)
        Bs[f] = __ldg(&gB[f]);
    __syncthreads();

    const int off = (b * PSSM_DIN + d) * PSSM_SEQ + c * PSSM_CL;
    const float* dl = g_delta + off;
    const float* ul = g_u + off;
    const float a21 = g_a2[lane];
    const float a22 = g_a2[lane + 32];

    float h1 = 0.f, h2 = 0.f, ds = 0.f;
    if (dir == 0) pssm_local_scan<false>(dl, ul, Bs, a21, a22, lane, h1, h2, ds);
    else          pssm_local_scan<true >(dl, ul, Bs, a21, a22, lane, h1, h2, ds);

    float* hl = g_hloc + ((((b * 2 + dir) * PSSM_NC + c) * PSSM_DIN + d) * PSSM_NST);
    hl[lane]      = h1;
    hl[lane + 32] = h2;
    if (dir == 0 && lane == 0)
        g_dS[(b * PSSM_NC + c) * PSSM_DIN + d] = ds;
}

// ============================================================
// Phase B: carry scan across 32 chunks per (b,dir,d,n).
// EXACTLY 32768 threads; idx = (((b*2+dir)*128)+d)*64+n
// ============================================================
__global__ void pssm_carry_kernel()
{
    const int idx = blockIdx.x * blockDim.x + threadIdx.x;   // 0..32767
    const int n   = idx & 63;
    const int d   = (idx >> 6) & 127;
    const int dir = (idx >> 13) & 1;
    const int b   = idx >> 14;

    const float a2n = g_a2[n];
    const int base = ((b * 2 + dir) * PSSM_NC) * PSSM_DIN * PSSM_NST + d * PSSM_NST + n;
    const int dsb  = b * PSSM_NC * PSSM_DIN + d;

    float prev = 0.f;
    #pragma unroll 8
    for (int cc = 0; cc < PSSM_NC; cc++) {
        const int c = dir ? (PSSM_NC - 1 - cc) : cc;
        const int o = base + c * PSSM_DIN * PSSM_NST;
        g_carry[o] = prev;
        const float E = exp2f(a2n * g_dS[dsb + c * PSSM_DIN]);
        prev = fmaf(E, prev, g_hloc[o]);
    }
}

// ============================================================
// Phase C: chunk scan seeded with carry + output y += sum_n C*h.
// Same grid as A. B/C interleaved float2 in shared.
// ============================================================
template<bool REV>
__device__ __forceinline__ void pssm_out_scan(
    const float* __restrict__ dl, const float* __restrict__ ul,
    const float2* __restrict__ BCs, float a21, float a22, int lane,
    float& h1, float& h2, float* __restrict__ yb)
{
    float acc = 0.f;
    #pragma unroll 4
    for (int s = 0; s < 16; s++) {
        const int lb = REV ? (60 - 4 * s) : 4 * s;
        const float4 d4 = __ldg((const float4*)(dl + lb));
        const float4 u4 = __ldg((const float4*)(ul + lb));
        const float da[4] = {d4.x, d4.y, d4.z, d4.w};
        const float ua[4] = {u4.x, u4.y, u4.z, u4.w};
        #pragma unroll
        for (int k = 0; k < 4; k++) {
            const int j = REV ? (3 - k) : k;
            const int l = lb + j;
            const float e1 = exp2f(da[j] * a21);
            const float e2 = exp2f(da[j] * a22);
            const float2 bc1 = BCs[l * PSSM_NST + lane];
            const float2 bc2 = BCs[l * PSSM_NST + lane + 32];
            h1 = fmaf(e1, h1, ua[j] * bc1.x);
            h2 = fmaf(e2, h2, ua[j] * bc2.x);
            float p = fmaf(h1, bc1.y, h2 * bc2.y);
            p += __shfl_xor_sync(0xffffffffu, p, 16);
            p += __shfl_xor_sync(0xffffffffu, p, 8);
            p += __shfl_xor_sync(0xffffffffu, p, 4);
            p += __shfl_xor_sync(0xffffffffu, p, 2);
            p += __shfl_xor_sync(0xffffffffu, p, 1);
            if (lane == (l & 31)) acc = p;
        }
        if (s == 7 || s == 15) {          // flush a 32-timestep group
            const int lg = REV ? (s == 7 ? 32 : 0) : (s == 7 ? 0 : 32);
            atomicAdd(&yb[(lg + lane) * PSSM_DIN], acc);
            acc = 0.f;
        }
    }
}

__global__ void __launch_bounds__(512) pssm_scanC_kernel(float* __restrict__ y)
{
    __shared__ float2 BCs[PSSM_CL * PSSM_NST];   // 32KB

    const int blk = blockIdx.x;
    const int dg  = blk & 7;
    const int c   = (blk >> 3) & 31;
    const int dir = (blk >> 8) & 1;
    const int b   = blk >> 9;

    const int warp = threadIdx.x >> 5;
    const int lane = threadIdx.x & 31;
    const int d    = dg * 16 + warp;

    const int gbase = (b * PSSM_SEQ + c * PSSM_CL) * PSSM_NST;
    const float* gB = g_B + gbase;
    const float* gC = g_C + gbase;
    for (int f = threadIdx.x; f < PSSM_CL * PSSM_NST; f += 512)
        BCs[f] = make_float2(__ldg(&gB[f]), __ldg(&gC[f]));
    __syncthreads();

    const int off = (b * PSSM_DIN + d) * PSSM_SEQ + c * PSSM_CL;
    const float* dl = g_delta + off;
    const float* ul = g_u + off;
    const float a21 = g_a2[lane];
    const float a22 = g_a2[lane + 32];

    const float* cr = g_carry + ((((b * 2 + dir) * PSSM_NC + c) * PSSM_DIN + d) * PSSM_NST);
    float h1 = cr[lane];
    float h2 = cr[lane + 32];

    float* yb = y + (size_t)(b * PSSM_SEQ + c * PSSM_CL) * PSSM_DIN + d;

    if (dir == 0) pssm_out_scan<false>(dl, ul, BCs, a21, a22, lane, h1, h2, yb);
    else          pssm_out_scan<true >(dl, ul, BCs, a21, a22, lane, h1, h2, yb);
}

// ============================================================
extern "C" void kernel_launch(void* const* d_in, const int* in_sizes, int n_in,
                              void* d_out, int out_size)
{
    const float* x  = (const float*)d_in[0];
    const float* W  = (const float*)d_in[1];
    const float* cw = (const float*)d_in[2];
    const float* cb = (const float*)d_in[3];
    const float* A  = (const float*)d_in[4];
    const float* Dp = (const float*)d_in[5];
    float* y = (float*)d_out;

    dim3 pg(32, 24);
    pssm_proj_kernel<<<pg, 128>>>(x, W, A);
    pssm_conv_kernel<<<(PSSM_BATCH * PSSM_DIN * PSSM_SEQ) / 256, 256>>>(cw, cb, Dp, y);
    pssm_scanA_kernel<<<1024, 512>>>();
    pssm_carry_kernel<<<128, 256>>>();   // FIX: exactly 32768 threads (was 65536 -> OOB)
    pssm_scanC_kernel<<<1024, 512>>>(y);
}

// round 6
// speedup vs baseline: 3.5042x; 1.2336x over previous
#include <cuda_runtime.h>

#define PSSM_BATCH  2
#define PSSM_SEQ    2048
#define PSSM_DIN    128
#define PSSM_NST    64
#define PSSM_NC     32      // chunks per sequence
#define PSSM_CL     64      // chunk length
#define PSSM_LOG2E  1.4426950408889634f

// ---- scratch (static device arrays; no allocation) ----
__device__ float g_xc   [PSSM_BATCH*PSSM_DIN*PSSM_SEQ];            // (b,d,l)
__device__ float g_delta[PSSM_BATCH*PSSM_DIN*PSSM_SEQ];            // (b,d,l) sigmoid applied
__device__ float g_u    [PSSM_BATCH*PSSM_DIN*PSSM_SEQ];            // (b,d,l) delta*x_conv
__device__ float g_v    [PSSM_BATCH*PSSM_DIN*PSSM_SEQ];            // (b,d,l) x_conv
__device__ float g_B    [PSSM_BATCH*PSSM_SEQ*PSSM_NST];            // (b,l,n)
__device__ float g_C    [PSSM_BATCH*PSSM_SEQ*PSSM_NST];            // (b,l,n)
__device__ float g_a2   [PSSM_NST];                                // rowsum(A)*log2(e)
__device__ float g_hloc [PSSM_BATCH*2*PSSM_NC*PSSM_DIN*PSSM_NST];  // (b,dir,c,d,n)
__device__ float g_carry[PSSM_BATCH*2*PSSM_NC*PSSM_DIN*PSSM_NST];  // (b,dir,c,d,n)
__device__ float g_dS   [PSSM_BATCH*PSSM_NC*PSSM_DIN];             // (b,c,d)

// ============================================================
// Stage 1: projection xp = x @ W^T, W tile staged in shared.
// grid (32, 24), block 128. token = bx*128+tx; 16 outputs/thread.
// ============================================================
__global__ void pssm_proj_kernel(const float* __restrict__ x,
                                 const float* __restrict__ W,
                                 const float* __restrict__ A)
{
    __shared__ float Ws[16 * 64];     // 4KB: this block's 16 W rows

    if (blockIdx.x == 0 && blockIdx.y == 0 && threadIdx.x < PSSM_NST) {
        float s = 0.f;
        const float* ar = A + threadIdx.x * PSSM_NST;
        #pragma unroll 8
        for (int j = 0; j < PSSM_NST; j++) s += ar[j];
        g_a2[threadIdx.x] = s * PSSM_LOG2E;
    }

    const int token = blockIdx.x * blockDim.x + threadIdx.x;   // 0..4095
    const int og    = blockIdx.y;                              // 0..23
    const int b = token >> 11;
    const int l = token & 2047;

    // stage W rows [og*16, og*16+16) into shared (256 float4, 2/thread)
    {
        const float4* wsrc = (const float4*)(W + og * 16 * 64);
        float4* wdst = (float4*)Ws;
        wdst[threadIdx.x]       = __ldg(&wsrc[threadIdx.x]);
        wdst[threadIdx.x + 128] = __ldg(&wsrc[threadIdx.x + 128]);
    }

    float4 xv[16];
    const float4* xr = (const float4*)(x + token * 64);
    #pragma unroll
    for (int i = 0; i < 16; i++) xv[i] = __ldg(&xr[i]);

    __syncthreads();

    #pragma unroll 2
    for (int i = 0; i < 16; i++) {
        const int o = og * 16 + i;
        const float4* wr = (const float4*)(Ws + i * 64);
        float a0 = 0.f, a1 = 0.f, a2 = 0.f, a3 = 0.f;
        #pragma unroll
        for (int k = 0; k < 16; k++) {
            float4 w4 = wr[k];
            a0 = fmaf(w4.x, xv[k].x, a0);
            a1 = fmaf(w4.y, xv[k].y, a1);
            a2 = fmaf(w4.z, xv[k].z, a2);
            a3 = fmaf(w4.w, xv[k].w, a3);
        }
        const float acc = (a0 + a1) + (a2 + a3);

        if (o < 128) {
            g_xc[(b * PSSM_DIN + o) * PSSM_SEQ + l] = acc;
        } else if (o < 256) {
            g_delta[(b * PSSM_DIN + (o - 128)) * PSSM_SEQ + l] =
                __fdividef(1.f, 1.f + __expf(-acc));
        } else if (o < 320) {
            g_B[(b * PSSM_SEQ + l) * PSSM_NST + (o - 256)] = acc;
        } else {
            g_C[(b * PSSM_SEQ + l) * PSSM_NST + (o - 320)] = acc;
        }
    }
}

// ============================================================
// Stage 2: depthwise causal conv (k=4) + bias.
// Writes v (=x_conv) and u (=delta*x_conv), both coalesced (b,d,l).
// ============================================================
__global__ void pssm_conv_kernel(const float* __restrict__ cw,
                                 const float* __restrict__ cb)
{
    const int idx = blockIdx.x * blockDim.x + threadIdx.x;   // (b,d,l) flat
    const int l  = idx & 2047;
    const int bd = idx >> 11;
    const int d  = bd & 127;

    const float* xc = g_xc + bd * PSSM_SEQ;
    const float w0 = __ldg(&cw[d * 4 + 0]);
    const float w1 = __ldg(&cw[d * 4 + 1]);
    const float w2 = __ldg(&cw[d * 4 + 2]);
    const float w3 = __ldg(&cw[d * 4 + 3]);

    float v = __ldg(&cb[d]);
    v = fmaf(w3, xc[l], v);
    if (l >= 1) v = fmaf(w2, xc[l - 1], v);
    if (l >= 2) v = fmaf(w1, xc[l - 2], v);
    if (l >= 3) v = fmaf(w0, xc[l - 3], v);

    g_v[idx] = v;
    g_u[idx] = g_delta[idx] * v;
}

// ============================================================
// Phase A: per-chunk local scan -> end state hloc, chunk delta-sum dS.
// grid 1024: blk = (b<<9)|(dir<<8)|(c<<3)|dg.  block 512 = 16 warps.
// warp -> d = dg*16 + warp; lane holds states (lane, lane+32).
// ============================================================
template<bool REV>
__device__ __forceinline__ void pssm_local_scan(
    const float* __restrict__ dl, const float* __restrict__ ul,
    const float* __restrict__ Bs, float a21, float a22, int lane,
    float& h1, float& h2, float& ds)
{
    #pragma unroll 4
    for (int s = 0; s < 16; s++) {
        const int lb = REV ? (60 - 4 * s) : 4 * s;
        const float4 d4 = __ldg((const float4*)(dl + lb));
        const float4 u4 = __ldg((const float4*)(ul + lb));
        const float da[4] = {d4.x, d4.y, d4.z, d4.w};
        const float ua[4] = {u4.x, u4.y, u4.z, u4.w};
        #pragma unroll
        for (int k = 0; k < 4; k++) {
            const int j = REV ? (3 - k) : k;          // compile-time
            const int l = lb + j;
            const float e1 = exp2f(da[j] * a21);
            const float e2 = exp2f(da[j] * a22);
            const float B1 = Bs[l * PSSM_NST + lane];
            const float B2 = Bs[l * PSSM_NST + lane + 32];
            h1 = fmaf(e1, h1, ua[j] * B1);
            h2 = fmaf(e2, h2, ua[j] * B2);
            ds += da[j];
        }
    }
}

__global__ void __launch_bounds__(512) pssm_scanA_kernel()
{
    __shared__ float Bs[PSSM_CL * PSSM_NST];   // 16KB

    const int blk = blockIdx.x;
    const int dg  = blk & 7;
    const int c   = (blk >> 3) & 31;
    const int dir = (blk >> 8) & 1;
    const int b   = blk >> 9;

    const int warp = threadIdx.x >> 5;
    const int lane = threadIdx.x & 31;
    const int d    = dg * 16 + warp;

    const float* gB = g_B + (b * PSSM_SEQ + c * PSSM_CL) * PSSM_NST;
    for (int f = threadIdx.x; f < PSSM_CL * PSSM_NST; f += 512)
        Bs[f] = __ldg(&gB[f]);
    __syncthreads();

    const int off = (b * PSSM_DIN + d) * PSSM_SEQ + c * PSSM_CL;
    const float* dl = g_delta + off;
    const float* ul = g_u + off;
    const float a21 = g_a2[lane];
    const float a22 = g_a2[lane + 32];

    float h1 = 0.f, h2 = 0.f, ds = 0.f;
    if (dir == 0) pssm_local_scan<false>(dl, ul, Bs, a21, a22, lane, h1, h2, ds);
    else          pssm_local_scan<true >(dl, ul, Bs, a21, a22, lane, h1, h2, ds);

    float* hl = g_hloc + ((((b * 2 + dir) * PSSM_NC + c) * PSSM_DIN + d) * PSSM_NST);
    hl[lane]      = h1;
    hl[lane + 32] = h2;
    if (dir == 0 && lane == 0)
        g_dS[(b * PSSM_NC + c) * PSSM_DIN + d] = ds;
}

// ============================================================
// Phase B: carry scan across 32 chunks per (b,dir,d,n).
// EXACTLY 32768 threads. Batched loads -> register scan -> stores.
// ============================================================
__global__ void pssm_carry_kernel()
{
    const int idx = blockIdx.x * blockDim.x + threadIdx.x;   // 0..32767
    const int n   = idx & 63;
    const int d   = (idx >> 6) & 127;
    const int dir = (idx >> 13) & 1;
    const int b   = idx >> 14;

    const float a2n = g_a2[n];
    const int base = ((b * 2 + dir) * PSSM_NC) * PSSM_DIN * PSSM_NST + d * PSSM_NST + n;
    const int dsb  = b * PSSM_NC * PSSM_DIN + d;

    float hl[PSSM_NC], E[PSSM_NC];
    #pragma unroll
    for (int c = 0; c < PSSM_NC; c++)
        hl[c] = g_hloc[base + c * PSSM_DIN * PSSM_NST];
    #pragma unroll
    for (int c = 0; c < PSSM_NC; c++)
        E[c] = exp2f(a2n * g_dS[dsb + c * PSSM_DIN]);

    float prev = 0.f;
    if (dir == 0) {
        #pragma unroll
        for (int c = 0; c < PSSM_NC; c++) {
            g_carry[base + c * PSSM_DIN * PSSM_NST] = prev;
            prev = fmaf(E[c], prev, hl[c]);
        }
    } else {
        #pragma unroll
        for (int c = PSSM_NC - 1; c >= 0; c--) {
            g_carry[base + c * PSSM_DIN * PSSM_NST] = prev;
            prev = fmaf(E[c], prev, hl[c]);
        }
    }
}

// ============================================================
// Phase C: chunk scan seeded with carry; both dirs of a d in one block.
// grid 1024: blk = (b<<9)|(c<<4)|dg16.  block 512 = 16 warps:
//   warp w -> d = dg*8 + (w>>1), dir = w&1.
// Reductions land in smem ysum[64][17] (col = warp id); then one
// coalesced pass writes y = fwd + bwd + D*v.  No atomics.
// ============================================================
template<bool REV>
__device__ __forceinline__ void pssm_out_scan(
    const float* __restrict__ dl, const float* __restrict__ ul,
    const float2* __restrict__ BCs, float a21, float a22, int lane,
    float h1, float h2, float* __restrict__ ys, int col)
{
    float acc = 0.f;
    #pragma unroll 4
    for (int s = 0; s < 16; s++) {
        const int lb = REV ? (60 - 4 * s) : 4 * s;
        const float4 d4 = __ldg((const float4*)(dl + lb));
        const float4 u4 = __ldg((const float4*)(ul + lb));
        const float da[4] = {d4.x, d4.y, d4.z, d4.w};
        const float ua[4] = {u4.x, u4.y, u4.z, u4.w};
        #pragma unroll
        for (int k = 0; k < 4; k++) {
            const int j = REV ? (3 - k) : k;
            const int l = lb + j;
            const float e1 = exp2f(da[j] * a21);
            const float e2 = exp2f(da[j] * a22);
            const float2 bc1 = BCs[l * PSSM_NST + lane];
            const float2 bc2 = BCs[l * PSSM_NST + lane + 32];
            h1 = fmaf(e1, h1, ua[j] * bc1.x);
            h2 = fmaf(e2, h2, ua[j] * bc2.x);
            float p = fmaf(h1, bc1.y, h2 * bc2.y);
            p += __shfl_xor_sync(0xffffffffu, p, 16);
            p += __shfl_xor_sync(0xffffffffu, p, 8);
            p += __shfl_xor_sync(0xffffffffu, p, 4);
            p += __shfl_xor_sync(0xffffffffu, p, 2);
            p += __shfl_xor_sync(0xffffffffu, p, 1);
            if (lane == (l & 31)) acc = p;
        }
        if (s == 7 || s == 15) {          // flush a 32-timestep group
            const int lg = REV ? (s == 7 ? 32 : 0) : (s == 7 ? 0 : 32);
            ys[(lg + lane) * 17 + col] = acc;
            acc = 0.f;
        }
    }
}

__global__ void __launch_bounds__(512) pssm_scanC_kernel(float* __restrict__ y,
                                                         const float* __restrict__ Dp)
{
    __shared__ float2 BCs[PSSM_CL * PSSM_NST];   // 32KB
    __shared__ float  ysum[PSSM_CL * 17];        // 4.25KB, col = warp (dl*2+dir)
    __shared__ float  vs[8 * 65];                // 2KB, x_conv tile (8 d x 64 l)

    const int blk = blockIdx.x;
    const int dg  = blk & 15;             // 16 groups of 8 d
    const int c   = (blk >> 4) & 31;
    const int b   = blk >> 9;

    const int tid  = threadIdx.x;
    const int warp = tid >> 5;
    const int lane = tid & 31;
    const int d    = dg * 8 + (warp >> 1);
    const int dir  = warp & 1;

    // stage B/C chunk
    const int gbase = (b * PSSM_SEQ + c * PSSM_CL) * PSSM_NST;
    const float* gB = g_B + gbase;
    const float* gC = g_C + gbase;
    for (int f = tid; f < PSSM_CL * PSSM_NST; f += 512)
        BCs[f] = make_float2(__ldg(&gB[f]), __ldg(&gC[f]));

    // stage x_conv tile: rows dg*8..dg*8+8, cols c*64..c*64+64 (coalesced)
    {
        const int r = tid >> 6, lv = tid & 63;
        vs[r * 65 + lv] =
            g_v[(b * PSSM_DIN + dg * 8 + r) * PSSM_SEQ + c * PSSM_CL + lv];
    }
    __syncthreads();

    const int off = (b * PSSM_DIN + d) * PSSM_SEQ + c * PSSM_CL;
    const float* dl = g_delta + off;
    const float* ul = g_u + off;
    const float a21 = g_a2[lane];
    const float a22 = g_a2[lane + 32];

    const float* cr = g_carry + ((((b * 2 + dir) * PSSM_NC + c) * PSSM_DIN + d) * PSSM_NST);
    const float h1 = cr[lane];
    const float h2 = cr[lane + 32];

    if (dir == 0) pssm_out_scan<false>(dl, ul, BCs, a21, a22, lane, h1, h2, ysum, warp);
    else          pssm_out_scan<true >(dl, ul, BCs, a21, a22, lane, h1, h2, ysum, warp);
    __syncthreads();

    // output: 512 cells = 64 l x 8 d, coalesced 32B-sector stores
    {
        const int l  = tid >> 3;
        const int dl2 = tid & 7;
        const int dd = dg * 8 + dl2;
        const float val = ysum[l * 17 + dl2 * 2] + ysum[l * 17 + dl2 * 2 + 1]
                        + __ldg(&Dp[dd]) * vs[dl2 * 65 + l];
        y[(size_t)(b * PSSM_SEQ + c * PSSM_CL + l) * PSSM_DIN + dd] = val;
    }
}

// ============================================================
extern "C" void kernel_launch(void* const* d_in, const int* in_sizes, int n_in,
                              void* d_out, int out_size)
{
    const float* x  = (const float*)d_in[0];
    const float* W  = (const float*)d_in[1];
    const float* cw = (const float*)d_in[2];
    const float* cb = (const float*)d_in[3];
    const float* A  = (const float*)d_in[4];
    const float* Dp = (const float*)d_in[5];
    float* y = (float*)d_out;

    dim3 pg(32, 24);
    pssm_proj_kernel<<<pg, 128>>>(x, W, A);
    pssm_conv_kernel<<<(PSSM_BATCH * PSSM_DIN * PSSM_SEQ) / 256, 256>>>(cw, cb);
    pssm_scanA_kernel<<<1024, 512>>>();
    pssm_carry_kernel<<<128, 256>>>();
    pssm_scanC_kernel<<<1024, 512>>>(y, Dp);
}

// round 7
// speedup vs baseline: 4.2365x; 1.2090x over previous
#include <cuda_runtime.h>

#define PSSM_BATCH  2
#define PSSM_SEQ    2048
#define PSSM_DIN    128
#define PSSM_NST    64
#define PSSM_NC     32      // chunks per sequence
#define PSSM_CL     64      // chunk length
#define PSSM_LOG2E  1.4426950408889634f

// ---- scratch (static device arrays; no allocation) ----
__device__ float g_xc   [PSSM_BATCH*PSSM_DIN*PSSM_SEQ];            // (b,d,l)
__device__ float g_delta[PSSM_BATCH*PSSM_DIN*PSSM_SEQ];            // (b,d,l) sigmoid applied
__device__ float g_u    [PSSM_BATCH*PSSM_DIN*PSSM_SEQ];            // (b,d,l) delta*x_conv
__device__ float g_v    [PSSM_BATCH*PSSM_DIN*PSSM_SEQ];            // (b,d,l) x_conv
__device__ float g_B    [PSSM_BATCH*PSSM_SEQ*PSSM_NST];            // (b,l,n)
__device__ float g_C    [PSSM_BATCH*PSSM_SEQ*PSSM_NST];            // (b,l,n)
__device__ float g_a2   [PSSM_NST];                                // rowsum(A)*log2(e)
__device__ float g_hloc [PSSM_BATCH*2*PSSM_NC*PSSM_DIN*PSSM_NST];  // (b,dir,c,d,n)
__device__ float g_carry[PSSM_BATCH*2*PSSM_NC*PSSM_DIN*PSSM_NST];  // (b,dir,c,d,n)
__device__ float g_dS   [PSSM_BATCH*PSSM_NC*PSSM_DIN];             // (b,c,d)

// ============================================================
// Stage 1: projection xp = x @ W^T.
// grid (64, 12), block 256.  bx -> 64-token tile, by -> 32 outputs.
// x tile staged TRANSPOSED in smem (conflict-free lane reads);
// W tile staged in smem (warp-uniform broadcast reads).
// thread (oc = tid>>6, t = tid&63) computes 8 outputs for token t.
// ============================================================
__global__ void __launch_bounds__(256) pssm_proj_kernel(
    const float* __restrict__ x,
    const float* __restrict__ W,
    const float* __restrict__ A)
{
    __shared__ float xsT[64 * 65];    // [k][t], pad 65  (16.6KB)
    __shared__ float Wsm[32 * 64];    // [i][k]          (8KB)

    const int tid = threadIdx.x;
    const int og  = blockIdx.y;                  // 0..11
    const int t0  = blockIdx.x * 64;             // global token base

    if (blockIdx.x == 0 && blockIdx.y == 0 && tid < PSSM_NST) {
        float s = 0.f;
        const float* ar = A + tid * PSSM_NST;
        #pragma unroll 8
        for (int j = 0; j < PSSM_NST; j++) s += ar[j];
        g_a2[tid] = s * PSSM_LOG2E;
    }

    // stage W rows [og*32, og*32+32): 512 float4, 2/thread
    {
        const float4* wsrc = (const float4*)(W + og * 32 * 64);
        float4* wdst = (float4*)Wsm;
        wdst[tid]       = __ldg(&wsrc[tid]);
        wdst[tid + 256] = __ldg(&wsrc[tid + 256]);
    }

    // stage x transposed: 1024 float4 coalesced loads, scatter to xsT
    #pragma unroll
    for (int i = 0; i < 4; i++) {
        const int f  = tid + 256 * i;
        const int t  = f >> 4;
        const int c4 = (f & 15) * 4;
        const float4 v = __ldg((const float4*)(x + (t0 + t) * 64 + c4));
        xsT[(c4 + 0) * 65 + t] = v.x;
        xsT[(c4 + 1) * 65 + t] = v.y;
        xsT[(c4 + 2) * 65 + t] = v.z;
        xsT[(c4 + 3) * 65 + t] = v.w;
    }
    __syncthreads();

    const int oc = tid >> 6;          // 0..3
    const int t  = tid & 63;
    const int token = t0 + t;
    const int b = token >> 11;
    const int l = token & 2047;

    float acc[8] = {0.f, 0.f, 0.f, 0.f, 0.f, 0.f, 0.f, 0.f};

    #pragma unroll 4
    for (int k4 = 0; k4 < 16; k4++) {
        const int k = k4 * 4;
        const float x0 = xsT[(k + 0) * 65 + t];
        const float x1 = xsT[(k + 1) * 65 + t];
        const float x2 = xsT[(k + 2) * 65 + t];
        const float x3 = xsT[(k + 3) * 65 + t];
        #pragma unroll
        for (int i = 0; i < 8; i++) {
            const float4 w4 = *(const float4*)&Wsm[(oc * 8 + i) * 64 + k];
            acc[i] = fmaf(w4.x, x0, acc[i]);
            acc[i] = fmaf(w4.y, x1, acc[i]);
            acc[i] = fmaf(w4.z, x2, acc[i]);
            acc[i] = fmaf(w4.w, x3, acc[i]);
        }
    }

    const int obase = og * 32 + oc * 8;          // block-uniform segment
    if (obase < 128) {                            // x_c_in
        #pragma unroll
        for (int i = 0; i < 8; i++)
            g_xc[(b * PSSM_DIN + obase + i) * PSSM_SEQ + l] = acc[i];
    } else if (obase < 256) {                     // delta (sigmoid)
        #pragma unroll
        for (int i = 0; i < 8; i++)
            g_delta[(b * PSSM_DIN + (obase - 128 + i)) * PSSM_SEQ + l] =
                __fdividef(1.f, 1.f + __expf(-acc[i]));
    } else if (obase < 320) {                     // B
        float4* dst = (float4*)&g_B[(b * PSSM_SEQ + l) * PSSM_NST + (obase - 256)];
        dst[0] = make_float4(acc[0], acc[1], acc[2], acc[3]);
        dst[1] = make_float4(acc[4], acc[5], acc[6], acc[7]);
    } else {                                      // C
        float4* dst = (float4*)&g_C[(b * PSSM_SEQ + l) * PSSM_NST + (obase - 320)];
        dst[0] = make_float4(acc[0], acc[1], acc[2], acc[3]);
        dst[1] = make_float4(acc[4], acc[5], acc[6], acc[7]);
    }
}

// ============================================================
// Stage 2: depthwise causal conv (k=4) + bias.
// Writes v (=x_conv) and u (=delta*x_conv), both coalesced (b,d,l).
// ============================================================
__global__ void pssm_conv_kernel(const float* __restrict__ cw,
                                 const float* __restrict__ cb)
{
    const int idx = blockIdx.x * blockDim.x + threadIdx.x;   // (b,d,l) flat
    const int l  = idx & 2047;
    const int bd = idx >> 11;
    const int d  = bd & 127;

    const float* xc = g_xc + bd * PSSM_SEQ;
    const float w0 = __ldg(&cw[d * 4 + 0]);
    const float w1 = __ldg(&cw[d * 4 + 1]);
    const float w2 = __ldg(&cw[d * 4 + 2]);
    const float w3 = __ldg(&cw[d * 4 + 3]);

    float v = __ldg(&cb[d]);
    v = fmaf(w3, xc[l], v);
    if (l >= 1) v = fmaf(w2, xc[l - 1], v);
    if (l >= 2) v = fmaf(w1, xc[l - 2], v);
    if (l >= 3) v = fmaf(w0, xc[l - 3], v);

    g_v[idx] = v;
    g_u[idx] = g_delta[idx] * v;
}

// ============================================================
// Phase A: per-chunk local scan -> end state hloc, chunk delta-sum dS.
// grid 1024: blk = (b<<9)|(dir<<8)|(c<<3)|dg.  block 512 = 16 warps.
// warp -> d = dg*16 + warp; lane holds states (lane, lane+32).
// ============================================================
template<bool REV>
__device__ __forceinline__ void pssm_local_scan(
    const float* __restrict__ dl, const float* __restrict__ ul,
    const float* __restrict__ Bs, float a21, float a22, int lane,
    float& h1, float& h2, float& ds)
{
    #pragma unroll 4
    for (int s = 0; s < 16; s++) {
        const int lb = REV ? (60 - 4 * s) : 4 * s;
        const float4 d4 = __ldg((const float4*)(dl + lb));
        const float4 u4 = __ldg((const float4*)(ul + lb));
        const float da[4] = {d4.x, d4.y, d4.z, d4.w};
        const float ua[4] = {u4.x, u4.y, u4.z, u4.w};
        #pragma unroll
        for (int k = 0; k < 4; k++) {
            const int j = REV ? (3 - k) : k;          // compile-time
            const int l = lb + j;
            const float e1 = exp2f(da[j] * a21);
            const float e2 = exp2f(da[j] * a22);
            const float B1 = Bs[l * PSSM_NST + lane];
            const float B2 = Bs[l * PSSM_NST + lane + 32];
            h1 = fmaf(e1, h1, ua[j] * B1);
            h2 = fmaf(e2, h2, ua[j] * B2);
            ds += da[j];
        }
    }
}

__global__ void __launch_bounds__(512) pssm_scanA_kernel()
{
    __shared__ float Bs[PSSM_CL * PSSM_NST];   // 16KB

    const int blk = blockIdx.x;
    const int dg  = blk & 7;
    const int c   = (blk >> 3) & 31;
    const int dir = (blk >> 8) & 1;
    const int b   = blk >> 9;

    const int warp = threadIdx.x >> 5;
    const int lane = threadIdx.x & 31;
    const int d    = dg * 16 + warp;

    const float* gB = g_B + (b * PSSM_SEQ + c * PSSM_CL) * PSSM_NST;
    for (int f = threadIdx.x; f < PSSM_CL * PSSM_NST; f += 512)
        Bs[f] = __ldg(&gB[f]);
    __syncthreads();

    const int off = (b * PSSM_DIN + d) * PSSM_SEQ + c * PSSM_CL;
    const float* dl = g_delta + off;
    const float* ul = g_u + off;
    const float a21 = g_a2[lane];
    const float a22 = g_a2[lane + 32];

    float h1 = 0.f, h2 = 0.f, ds = 0.f;
    if (dir == 0) pssm_local_scan<false>(dl, ul, Bs, a21, a22, lane, h1, h2, ds);
    else          pssm_local_scan<true >(dl, ul, Bs, a21, a22, lane, h1, h2, ds);

    float* hl = g_hloc + ((((b * 2 + dir) * PSSM_NC + c) * PSSM_DIN + d) * PSSM_NST);
    hl[lane]      = h1;
    hl[lane + 32] = h2;
    if (dir == 0 && lane == 0)
        g_dS[(b * PSSM_NC + c) * PSSM_DIN + d] = ds;
}

// ============================================================
// Phase B: carry scan across 32 chunks per (b,dir,d,n).
// EXACTLY 32768 threads. Batched loads -> register scan -> stores.
// ============================================================
__global__ void pssm_carry_kernel()
{
    const int idx = blockIdx.x * blockDim.x + threadIdx.x;   // 0..32767
    const int n   = idx & 63;
    const int d   = (idx >> 6) & 127;
    const int dir = (idx >> 13) & 1;
    const int b   = idx >> 14;

    const float a2n = g_a2[n];
    const int base = ((b * 2 + dir) * PSSM_NC) * PSSM_DIN * PSSM_NST + d * PSSM_NST + n;
    const int dsb  = b * PSSM_NC * PSSM_DIN + d;

    float hl[PSSM_NC], E[PSSM_NC];
    #pragma unroll
    for (int c = 0; c < PSSM_NC; c++)
        hl[c] = g_hloc[base + c * PSSM_DIN * PSSM_NST];
    #pragma unroll
    for (int c = 0; c < PSSM_NC; c++)
        E[c] = exp2f(a2n * g_dS[dsb + c * PSSM_DIN]);

    float prev = 0.f;
    if (dir == 0) {
        #pragma unroll
        for (int c = 0; c < PSSM_NC; c++) {
            g_carry[base + c * PSSM_DIN * PSSM_NST] = prev;
            prev = fmaf(E[c], prev, hl[c]);
        }
    } else {
        #pragma unroll
        for (int c = PSSM_NC - 1; c >= 0; c--) {
            g_carry[base + c * PSSM_DIN * PSSM_NST] = prev;
            prev = fmaf(E[c], prev, hl[c]);
        }
    }
}

// ============================================================
// Phase C: chunk scan seeded with carry; warp = one d, BOTH dirs:
//   half-warp g=0 runs fwd, g=1 runs bwd; lane r=lane&15 holds
//   states (r, r+16, r+32, r+48).  Block = 16 warps = 16 d.
// grid 512: blk = (b<<8)|(c<<3)|dg.  No atomics.
// ============================================================
__global__ void __launch_bounds__(512) pssm_scanC_kernel(float* __restrict__ y,
                                                         const float* __restrict__ Dp)
{
    __shared__ float2 BCs[PSSM_CL * PSSM_NST];   // 32KB
    __shared__ float  ysum[PSSM_CL * 33];        // 8.25KB, col = warp*2 + dir
    __shared__ float  vs[16 * 65];               // 4.1KB, x_conv tile (16 d x 64 l)

    const int blk = blockIdx.x;
    const int dg  = blk & 7;              // 8 groups of 16 d
    const int c   = (blk >> 3) & 31;
    const int b   = blk >> 8;

    const int tid  = threadIdx.x;
    const int w    = tid >> 5;            // warp -> d
    const int lane = tid & 31;
    const int g    = lane >> 4;           // 0 = fwd, 1 = bwd
    const int r    = lane & 15;
    const int d    = dg * 16 + w;

    // stage B/C chunk
    const int gbase = (b * PSSM_SEQ + c * PSSM_CL) * PSSM_NST;
    const float* gB = g_B + gbase;
    const float* gC = g_C + gbase;
    for (int f = tid; f < PSSM_CL * PSSM_NST; f += 512)
        BCs[f] = make_float2(__ldg(&gB[f]), __ldg(&gC[f]));

    // stage x_conv tile: 16 d x 64 l, coalesced
    #pragma unroll
    for (int i = 0; i < 2; i++) {
        const int e  = tid + 512 * i;
        const int dd = e >> 6, lv = e & 63;
        vs[dd * 65 + lv] =
            g_v[(b * PSSM_DIN + dg * 16 + dd) * PSSM_SEQ + c * PSSM_CL + lv];
    }
    __syncthreads();

    const int off = (b * PSSM_DIN + d) * PSSM_SEQ + c * PSSM_CL;
    const float* dl = g_delta + off;
    const float* ul = g_u + off;
    const float a20 = g_a2[r];
    const float a21 = g_a2[r + 16];
    const float a22 = g_a2[r + 32];
    const float a23 = g_a2[r + 48];

    const float* cr = g_carry +
        ((((b * 2 + g) * PSSM_NC + c) * PSSM_DIN + d) * PSSM_NST);
    float h0 = cr[r];
    float h1 = cr[r + 16];
    float h2 = cr[r + 32];
    float h3 = cr[r + 48];

    float acc = 0.f;
    #pragma unroll 4
    for (int s = 0; s < 16; s++) {
        const int l0 = g ? (60 - 4 * s) : (4 * s);     // per-lane
        const float4 d4 = __ldg((const float4*)(dl + l0));
        const float4 u4 = __ldg((const float4*)(ul + l0));
        const float da[4] = {d4.x, d4.y, d4.z, d4.w};
        const float ua[4] = {u4.x, u4.y, u4.z, u4.w};
        #pragma unroll
        for (int k = 0; k < 4; k++) {
            const float dj = g ? da[3 - k] : da[k];    // both indices static
            const float uj = g ? ua[3 - k] : ua[k];
            const int   l  = l0 + (g ? (3 - k) : k);
            const float e0 = exp2f(dj * a20);
            const float e1 = exp2f(dj * a21);
            const float e2 = exp2f(dj * a22);
            const float e3 = exp2f(dj * a23);
            const float2 bc0 = BCs[l * PSSM_NST + r];
            const float2 bc1 = BCs[l * PSSM_NST + r + 16];
            const float2 bc2 = BCs[l * PSSM_NST + r + 32];
            const float2 bc3 = BCs[l * PSSM_NST + r + 48];
            h0 = fmaf(e0, h0, uj * bc0.x);
            h1 = fmaf(e1, h1, uj * bc1.x);
            h2 = fmaf(e2, h2, uj * bc2.x);
            h3 = fmaf(e3, h3, uj * bc3.x);
            float p = h0 * bc0.y;
            p = fmaf(h1, bc1.y, p);
            p = fmaf(h2, bc2.y, p);
            p = fmaf(h3, bc3.y, p);
            p += __shfl_xor_sync(0xffffffffu, p, 8);
            p += __shfl_xor_sync(0xffffffffu, p, 4);
            p += __shfl_xor_sync(0xffffffffu, p, 2);
            p += __shfl_xor_sync(0xffffffffu, p, 1);
            if (r == (l & 15)) acc = p;
        }
        if ((s & 3) == 3) {               // flush a 16-timestep group
            const int grp = s >> 2;
            const int lg  = g ? (48 - 16 * grp) : (16 * grp);
            ysum[(lg + r) * 33 + w * 2 + g] = acc;
            acc = 0.f;
        }
    }
    __syncthreads();

    // output: 1024 cells = 64 l x 16 d, 2 per thread, coalesced stores
    #pragma unroll
    for (int i = 0; i < 2; i++) {
        const int cell = tid + 512 * i;
        const int l  = cell >> 4;
        const int dd = cell & 15;
        const int dglob = dg * 16 + dd;
        const float val = ysum[l * 33 + dd * 2] + ysum[l * 33 + dd * 2 + 1]
                        + __ldg(&Dp[dglob]) * vs[dd * 65 + l];
        y[(size_t)(b * PSSM_SEQ + c * PSSM_CL + l) * PSSM_DIN + dglob] = val;
    }
}

// ============================================================
extern "C" void kernel_launch(void* const* d_in, const int* in_sizes, int n_in,
                              void* d_out, int out_size)
{
    const float* x  = (const float*)d_in[0];
    const float* W  = (const float*)d_in[1];
    const float* cw = (const float*)d_in[2];
    const float* cb = (const float*)d_in[3];
    const float* A  = (const float*)d_in[4];
    const float* Dp = (const float*)d_in[5];
    float* y = (float*)d_out;

    dim3 pg(64, 12);
    pssm_proj_kernel<<<pg, 256>>>(x, W, A);
    pssm_conv_kernel<<<(PSSM_BATCH * PSSM_DIN * PSSM_SEQ) / 256, 256>>>(cw, cb);
    pssm_scanA_kernel<<<1024, 512>>>();
    pssm_carry_kernel<<<128, 256>>>();
    pssm_scanC_kernel<<<512, 512>>>(y, Dp);
}